// round 6
// baseline (speedup 1.0000x reference)
#include <cuda_runtime.h>
#include <cuda_bf16.h>

// Problem shape (fixed per metadata): B=32, D=16, H=W=256, N=512.
#define B_ 32
#define D_ 16
#define HW_ 256
#define N_ 512

// Self-cleaning cross-block accumulator (module-load zeroed; every launch
// restores the zero state, so graph replays are deterministic).
__device__ float g_part = 0.0f;
__device__ unsigned g_cnt = 0u;

// Upper-triangle job list over 8x8 grid of 64-row tiles (36 jobs/batch).
__constant__ unsigned char JOB_TI[36] = {
    0,0,0,0,0,0,0,0, 1,1,1,1,1,1,1, 2,2,2,2,2,2,
    3,3,3,3,3, 4,4,4,4, 5,5,5, 6,6, 7};
__constant__ unsigned char JOB_TJ[36] = {
    0,1,2,3,4,5,6,7, 1,2,3,4,5,6,7, 2,3,4,5,6,7,
    3,4,5,6,7, 4,5,6,7, 5,6,7, 6,7, 7};

// ---------------------------------------------------------------------------
// Fused kernel: gather + all-pairs loss, balanced 64x64 tile jobs.
// grid = (B=32, 9), 256 threads, 2 blocks/SM -> one wave on 144 SMs.
// Phase A: each block gathers its batch's 512 keypoint embeddings directly
//          from pred (2 keypoints/thread, 16 strided loads each, MLP=32),
//          pre-scaled by 1/sqrt(D); meta {sq, mask, tag} in SMEM slot 4.
// Phase B: 4 jobs of 64x64 pairs; thread = 4 rows (stride 16) x 4 cols.
//          Upper-triangle symmetry: diag tile weight 1, off-diag weight 2.
// Phase C: block partial -> g_part; 288th block writes *out and resets state.
// SMEM rows padded to 5 float4 (80B) -> conflict-free.
// ---------------------------------------------------------------------------
__global__ __launch_bounds__(256, 2) void tagloss_fused_kernel(
        const float* __restrict__ pred,
        const float* __restrict__ kpt,
        const int* __restrict__ vis,
        const int* __restrict__ tag,
        float* __restrict__ out) {
    __shared__ float4 sE[N_ * 5];   // 40 KB: [row][0..3]=embedding, [4]=meta
    __shared__ float wsum[8];
    __shared__ float kwsum[8];

    const int b = blockIdx.x;
    const int jb = blockIdx.y;
    const int t = threadIdx.x;

    // ---- Phase A: gather 2 keypoints per thread straight from pred ----
    float kp = 0.0f;
#pragma unroll
    for (int k = 0; k < 2; ++k) {
        const int n = t + k * 256;
        const int bn = b * N_ + n;
        const float2 kc = ((const float2*)kpt)[bn];
        const int y = (int)floorf(kc.x * (float)HW_);
        const int x = (int)floorf(kc.y * (float)HW_);
        const float* p = pred + ((size_t)b * D_ * HW_ * HW_) + (size_t)y * HW_ + x;
        float e[D_];
#pragma unroll
        for (int d = 0; d < D_; ++d)
            e[d] = p[(size_t)d * HW_ * HW_] * 0.25f;   // 1/sqrt(D), D=16
        float sq = 0.0f;
#pragma unroll
        for (int d = 0; d < D_; ++d) sq = fmaf(e[d], e[d], sq);
#pragma unroll
        for (int j = 0; j < 4; ++j)
            sE[n * 5 + j] = make_float4(e[4*j+0], e[4*j+1], e[4*j+2], e[4*j+3]);
        const float maskf = (vis[bn] > 0) ? 1.0f : 0.0f;
        sE[n * 5 + 4] = make_float4(sq, maskf, (float)tag[bn], 0.0f);
        kp += maskf;
    }
#pragma unroll
    for (int s = 16; s > 0; s >>= 1)
        kp += __shfl_xor_sync(0xFFFFFFFFu, kp, s);
    if ((t & 31) == 0) kwsum[t >> 5] = kp;
    __syncthreads();

    // ---- Phase B: 4 balanced 64x64 tile jobs ----
    float accT = 0.0f;
#pragma unroll
    for (int jk = 0; jk < 4; ++jk) {
        const int q = jb * 4 + jk;
        const int ti = JOB_TI[q];
        const int tj = JOB_TJ[q];
        const float w = (ti == tj) ? 1.0f : 2.0f;

        const int rbase = ti * 64 + (t & 15);        // rows strided by 16
        const int cbase = tj * 64 + (t >> 4) * 4;    // 4 consecutive cols

        float4 A[4][4];
        float rsq[4], rtag[4], rmask[4];
#pragma unroll
        for (int rr = 0; rr < 4; ++rr) {
            const int r = rbase + rr * 16;
#pragma unroll
            for (int j = 0; j < 4; ++j) A[rr][j] = sE[r * 5 + j];
            const float4 m = sE[r * 5 + 4];
            rsq[rr] = m.x; rmask[rr] = m.y; rtag[rr] = m.z;
        }

        float acc[4] = {0.0f, 0.0f, 0.0f, 0.0f};
#pragma unroll
        for (int cc = 0; cc < 4; ++cc) {
            const int c = cbase + cc;
            const float4 B0 = sE[c * 5 + 0];
            const float4 B1 = sE[c * 5 + 1];
            const float4 B2 = sE[c * 5 + 2];
            const float4 B3 = sE[c * 5 + 3];
            const float4 cm = sE[c * 5 + 4];
#pragma unroll
            for (int rr = 0; rr < 4; ++rr) {
                float d0, d1;
                d0 = A[rr][0].x * B0.x;
                d1 = A[rr][0].y * B0.y;
                d0 = fmaf(A[rr][0].z, B0.z, d0);
                d1 = fmaf(A[rr][0].w, B0.w, d1);
                d0 = fmaf(A[rr][1].x, B1.x, d0);
                d1 = fmaf(A[rr][1].y, B1.y, d1);
                d0 = fmaf(A[rr][1].z, B1.z, d0);
                d1 = fmaf(A[rr][1].w, B1.w, d1);
                d0 = fmaf(A[rr][2].x, B2.x, d0);
                d1 = fmaf(A[rr][2].y, B2.y, d1);
                d0 = fmaf(A[rr][2].z, B2.z, d0);
                d1 = fmaf(A[rr][2].w, B2.w, d1);
                d0 = fmaf(A[rr][3].x, B3.x, d0);
                d1 = fmaf(A[rr][3].y, B3.y, d1);
                d0 = fmaf(A[rr][3].z, B3.z, d0);
                d1 = fmaf(A[rr][3].w, B3.w, d1);
                const float dot = d0 + d1;
                const float e = fmaf(-2.0f, dot, rsq[rr] + cm.x);
                const float s = __fdividef(2.0f, 1.0f + __expf(e));
                const float tt = (rtag[rr] == cm.z) ? 1.0f : 0.0f;
                const float d = s - tt;
                acc[rr] = fmaf(cm.y, d * d, acc[rr]);
            }
        }
        accT += w * (rmask[0] * acc[0] + rmask[1] * acc[1] +
                     rmask[2] * acc[2] + rmask[3] * acc[3]);
    }

    // ---- Phase C: block reduction + cross-block accumulation ----
#pragma unroll
    for (int s = 16; s > 0; s >>= 1)
        accT += __shfl_xor_sync(0xFFFFFFFFu, accT, s);
    if ((t & 31) == 0) wsum[t >> 5] = accT;
    __syncthreads();
    if (t == 0) {
        float total = 0.0f, K = 0.0f;
#pragma unroll
        for (int w = 0; w < 8; ++w) { total += wsum[w]; K += kwsum[w]; }
        const float scale = 10.0f / (fmaxf(K * K, 1.0f) * (float)B_);
        atomicAdd(&g_part, total * scale);
        __threadfence();
        const unsigned done = atomicAdd(&g_cnt, 1u);
        if (done == (unsigned)(B_ * 9 - 1)) {
            // Last block: fetch-and-reset accumulator, publish result,
            // restore zero state for the next (graph-replayed) launch.
            const float result = atomicExch(&g_part, 0.0f);
            *out = result;
            __threadfence();
            atomicExch(&g_cnt, 0u);
        }
    }
}

extern "C" void kernel_launch(void* const* d_in, const int* in_sizes, int n_in,
                              void* d_out, int out_size) {
    const float* pred = (const float*)d_in[0];
    const float* kpt  = (const float*)d_in[1];
    const int*   vis  = (const int*)d_in[2];
    const int*   tag  = (const int*)d_in[3];
    float* out = (float*)d_out;

    dim3 grid(B_, 9);
    tagloss_fused_kernel<<<grid, 256>>>(pred, kpt, vis, tag, out);
}

// round 8
// speedup vs baseline: 1.1528x; 1.1528x over previous
#include <cuda_runtime.h>
#include <cuda_bf16.h>

// Problem shape (fixed per metadata): B=32, D=16, H=W=256, N=512.
#define B_ 32
#define D_ 16
#define HW_ 256
#define N_ 512

// Global staging: [B][N][5] float4 — slots 0..3 embedding (pre-scaled by
// 1/sqrt(D)), slot 4 meta {sq, mask, tag, 0}. Contiguous 40KB per batch.
__device__ float4 g_ebd[B_ * N_ * 5];

// Self-cleaning cross-block state (module-load zeroed; the last block of
// every launch restores zeros, so graph replays are deterministic).
__device__ float g_part = 0.0f;
__device__ unsigned g_cnt = 0u;
__device__ unsigned g_done[B_];   // per-batch gather-slice completion count

// Upper-triangle job list over 8x8 grid of 64-row tiles (36 jobs/batch).
__constant__ unsigned char JOB_TI[36] = {
    0,0,0,0,0,0,0,0, 1,1,1,1,1,1,1, 2,2,2,2,2,2,
    3,3,3,3,3, 4,4,4,4, 5,5,5, 6,6, 7};
__constant__ unsigned char JOB_TJ[36] = {
    0,1,2,3,4,5,6,7, 1,2,3,4,5,6,7, 2,3,4,5,6,7,
    3,4,5,6,7, 4,5,6,7, 5,6,7, 6,7, 7};

// ---------------------------------------------------------------------------
// Fused producer/consumer kernel. grid=(32,9), 256 thr, 2 blocks/SM: all 288
// blocks resident in one wave -> spin-wait across blocks is safe.
// Phase A: block (b,jb) gathers slice jb (<=57 rows) of batch b from pred,
//          then ALL threads fence (release) before t0 publishes the flag.
// Phase B: wait for all 9 slices, stage 40KB tile via __ldcg (L2-coherent),
//          then 4 balanced 64x64 tile jobs.
// Phase C: cross-block accumulation; 288th block publishes + resets state.
// SMEM rows padded to 5 float4 (80B) -> conflict-free.
// ---------------------------------------------------------------------------
__global__ __launch_bounds__(256, 2) void tagloss_fused_kernel(
        const float* __restrict__ pred,
        const float* __restrict__ kpt,
        const int* __restrict__ vis,
        const int* __restrict__ tag,
        float* __restrict__ out) {
    __shared__ float4 sE[N_ * 5];   // 40 KB
    __shared__ float wsum[8];
    __shared__ float kwsum[8];

    const int b = blockIdx.x;
    const int jb = blockIdx.y;
    const int t = threadIdx.x;

    // ---- Phase A: gather this block's slice of batch b ----
    {
        const int rbeg = jb * 57;
        const int rend = (rbeg + 57 < N_) ? (rbeg + 57) : N_;
        const int n = rbeg + t;
        if (n < rend) {
            const int bn = b * N_ + n;
            const float2 kc = ((const float2*)kpt)[bn];
            const int y = (int)floorf(kc.x * (float)HW_);
            const int x = (int)floorf(kc.y * (float)HW_);
            const float* p = pred + ((size_t)b * D_ * HW_ * HW_)
                           + (size_t)y * HW_ + x;
            float e[D_];
#pragma unroll
            for (int d = 0; d < D_; ++d)
                e[d] = p[(size_t)d * HW_ * HW_] * 0.25f;   // 1/sqrt(16)
            float sq = 0.0f;
#pragma unroll
            for (int d = 0; d < D_; ++d) sq = fmaf(e[d], e[d], sq);
            float4* row = &g_ebd[bn * 5];
#pragma unroll
            for (int j = 0; j < 4; ++j)
                row[j] = make_float4(e[4*j+0], e[4*j+1], e[4*j+2], e[4*j+3]);
            const float maskf = (vis[bn] > 0) ? 1.0f : 0.0f;
            row[4] = make_float4(sq, maskf, (float)tag[bn], 0.0f);
        }
        // Release: EVERY thread fences its own stores, barrier orders the
        // fences before t0's flag update.
        __threadfence();
        __syncthreads();
        if (t == 0) atomicAdd(&g_done[b], 1u);
    }

    // ---- Acquire: wait for all 9 slices of batch b ----
    if (t == 0) {
        while (atomicAdd(&g_done[b], 0u) < 9u) __nanosleep(40);
        __threadfence();
    }
    __syncthreads();

    // ---- Stage the 40KB batch tile from L2 (bypass L1: __ldcg) ----
    {
        const float4* gb = &g_ebd[b * N_ * 5];
#pragma unroll
        for (int k = 0; k < 10; ++k)         // 2560 float4 / 256 threads
            sE[t + k * 256] = __ldcg(gb + t + k * 256);
    }
    __syncthreads();

    // K = sum(mask): 2 staged rows per thread, AFTER the staging barrier.
    float kp = sE[(t * 2) * 5 + 4].y + sE[(t * 2 + 1) * 5 + 4].y;
#pragma unroll
    for (int s = 16; s > 0; s >>= 1)
        kp += __shfl_xor_sync(0xFFFFFFFFu, kp, s);
    if ((t & 31) == 0) kwsum[t >> 5] = kp;

    // ---- Phase B: 4 balanced 64x64 tile jobs ----
    float accT = 0.0f;
#pragma unroll
    for (int jk = 0; jk < 4; ++jk) {
        const int q = jb * 4 + jk;
        const int ti = JOB_TI[q];
        const int tj = JOB_TJ[q];
        const float w = (ti == tj) ? 1.0f : 2.0f;

        const int rbase = ti * 64 + (t & 15);        // rows strided by 16
        const int cbase = tj * 64 + (t >> 4) * 4;    // 4 consecutive cols

        float4 A[4][4];
        float rsq[4], rtag[4], rmask[4];
#pragma unroll
        for (int rr = 0; rr < 4; ++rr) {
            const int r = rbase + rr * 16;
#pragma unroll
            for (int j = 0; j < 4; ++j) A[rr][j] = sE[r * 5 + j];
            const float4 m = sE[r * 5 + 4];
            rsq[rr] = m.x; rmask[rr] = m.y; rtag[rr] = m.z;
        }

        float acc[4] = {0.0f, 0.0f, 0.0f, 0.0f};
#pragma unroll
        for (int cc = 0; cc < 4; ++cc) {
            const int c = cbase + cc;
            const float4 B0 = sE[c * 5 + 0];
            const float4 B1 = sE[c * 5 + 1];
            const float4 B2 = sE[c * 5 + 2];
            const float4 B3 = sE[c * 5 + 3];
            const float4 cm = sE[c * 5 + 4];
#pragma unroll
            for (int rr = 0; rr < 4; ++rr) {
                float d0, d1;
                d0 = A[rr][0].x * B0.x;
                d1 = A[rr][0].y * B0.y;
                d0 = fmaf(A[rr][0].z, B0.z, d0);
                d1 = fmaf(A[rr][0].w, B0.w, d1);
                d0 = fmaf(A[rr][1].x, B1.x, d0);
                d1 = fmaf(A[rr][1].y, B1.y, d1);
                d0 = fmaf(A[rr][1].z, B1.z, d0);
                d1 = fmaf(A[rr][1].w, B1.w, d1);
                d0 = fmaf(A[rr][2].x, B2.x, d0);
                d1 = fmaf(A[rr][2].y, B2.y, d1);
                d0 = fmaf(A[rr][2].z, B2.z, d0);
                d1 = fmaf(A[rr][2].w, B2.w, d1);
                d0 = fmaf(A[rr][3].x, B3.x, d0);
                d1 = fmaf(A[rr][3].y, B3.y, d1);
                d0 = fmaf(A[rr][3].z, B3.z, d0);
                d1 = fmaf(A[rr][3].w, B3.w, d1);
                const float dot = d0 + d1;
                const float e = fmaf(-2.0f, dot, rsq[rr] + cm.x);
                const float s = __fdividef(2.0f, 1.0f + __expf(e));
                const float tt = (rtag[rr] == cm.z) ? 1.0f : 0.0f;
                const float d = s - tt;
                acc[rr] = fmaf(cm.y, d * d, acc[rr]);
            }
        }
        accT += w * (rmask[0] * acc[0] + rmask[1] * acc[1] +
                     rmask[2] * acc[2] + rmask[3] * acc[3]);
    }

    // ---- Phase C: block reduction + cross-block accumulation ----
#pragma unroll
    for (int s = 16; s > 0; s >>= 1)
        accT += __shfl_xor_sync(0xFFFFFFFFu, accT, s);
    if ((t & 31) == 0) wsum[t >> 5] = accT;
    __syncthreads();
    if (t == 0) {
        float total = 0.0f, K = 0.0f;
#pragma unroll
        for (int w = 0; w < 8; ++w) { total += wsum[w]; K += kwsum[w]; }
        const float scale = 10.0f / (fmaxf(K * K, 1.0f) * (float)B_);
        atomicAdd(&g_part, total * scale);
        __threadfence();
        const unsigned done = atomicAdd(&g_cnt, 1u);
        if (done == (unsigned)(B_ * 9 - 1)) {
            // Last block (all other blocks have finished Phase B/C):
            // publish and restore zero state for the next graph replay.
            const float result = atomicExch(&g_part, 0.0f);
            *out = result;
#pragma unroll
            for (int bb = 0; bb < B_; ++bb) g_done[bb] = 0u;
            __threadfence();
            atomicExch(&g_cnt, 0u);
        }
    }
}

extern "C" void kernel_launch(void* const* d_in, const int* in_sizes, int n_in,
                              void* d_out, int out_size) {
    const float* pred = (const float*)d_in[0];
    const float* kpt  = (const float*)d_in[1];
    const int*   vis  = (const int*)d_in[2];
    const int*   tag  = (const int*)d_in[3];
    float* out = (float*)d_out;

    dim3 grid(B_, 9);
    tagloss_fused_kernel<<<grid, 256>>>(pred, kpt, vis, tag, out);
}

// round 11
// speedup vs baseline: 1.4098x; 1.2229x over previous
#include <cuda_runtime.h>
#include <cuda_bf16.h>

// Problem shape (fixed per metadata): B=32, D=16, H=W=256, N=512.
#define B_ 32
#define D_ 16
#define HW_ 256
#define N_ 512

// Staging: [B][N][5] float4 — slots 0..3 embedding (pre-scaled by 1/sqrt(D)),
// slot 4 meta {sq, mask, tag, 0}.
__device__ float4 g_ebd[B_ * N_ * 5];

// Upper-triangle job list over 8x8 grid of 64-row tiles (36 jobs/batch).
__constant__ unsigned char JOB_TI[36] = {
    0,0,0,0,0,0,0,0, 1,1,1,1,1,1,1, 2,2,2,2,2,2,
    3,3,3,3,3, 4,4,4,4, 5,5,5, 6,6, 7};
__constant__ unsigned char JOB_TJ[36] = {
    0,1,2,3,4,5,6,7, 1,2,3,4,5,6,7, 2,3,4,5,6,7,
    3,4,5,6,7, 4,5,6,7, 5,6,7, 6,7, 7};

// ---- f32x2 packed helpers (sm_10x FFMA2 path) ----
__device__ __forceinline__ unsigned long long pk2(float lo, float hi) {
    unsigned long long r;
    asm("mov.b64 %0, {%1, %2};" : "=l"(r) : "f"(lo), "f"(hi));
    return r;
}
__device__ __forceinline__ unsigned long long mul2(unsigned long long a,
                                                   unsigned long long b) {
    unsigned long long d;
    asm("mul.rn.f32x2 %0, %1, %2;" : "=l"(d) : "l"(a), "l"(b));
    return d;
}
__device__ __forceinline__ void fma2(unsigned long long& d,
                                     unsigned long long a,
                                     unsigned long long b) {
    asm("fma.rn.f32x2 %0, %1, %2, %3;" : "=l"(d) : "l"(a), "l"(b), "l"(d));
}
__device__ __forceinline__ unsigned long long add2(unsigned long long a,
                                                   unsigned long long b) {
    unsigned long long d;
    asm("add.rn.f32x2 %0, %1, %2;" : "=l"(d) : "l"(a), "l"(b));
    return d;
}
__device__ __forceinline__ float hsum2(unsigned long long v) {
    float lo, hi;
    asm("mov.b64 {%0, %1}, %2;" : "=f"(lo), "=f"(hi) : "l"(v));
    return lo + hi;
}
__device__ __forceinline__ float tanh_approx(float x) {
    float y;
    asm("tanh.approx.f32 %0, %1;" : "=f"(y) : "f"(x));
    return y;
}

// ---------------------------------------------------------------------------
// Kernel 1: flat gather — one thread per keypoint, spread across the chip.
// ---------------------------------------------------------------------------
__global__ __launch_bounds__(128) void tagloss_gather_kernel(
        const float* __restrict__ pred,
        const float* __restrict__ kpt,
        const int* __restrict__ vis,
        const int* __restrict__ tag,
        float* __restrict__ out) {
    const int bn = blockIdx.x * 128 + threadIdx.x;   // 0 .. B*N-1
    const int b = bn >> 9;

    const float2 k = ((const float2*)kpt)[bn];
    const int y = (int)floorf(k.x * (float)HW_);
    const int x = (int)floorf(k.y * (float)HW_);

    const float* p = pred + ((size_t)b * D_ * HW_ * HW_) + (size_t)y * HW_ + x;
    float e[D_];
    float sq = 0.0f;
#pragma unroll
    for (int d = 0; d < D_; ++d) {
        float v = p[(size_t)d * HW_ * HW_] * 0.25f;  // 1/sqrt(D), D=16
        e[d] = v;
        sq = fmaf(v, v, sq);
    }

    float4* row = &g_ebd[bn * 5];
#pragma unroll
    for (int j = 0; j < 4; ++j)
        row[j] = make_float4(e[4*j+0], e[4*j+1], e[4*j+2], e[4*j+3]);
    const float maskf = (vis[bn] > 0) ? 1.0f : 0.0f;
    row[4] = make_float4(sq, maskf, (float)tag[bn], 0.0f);

    if (bn == 0) *out = 0.0f;   // zero the poisoned output before accumulation
}

// ---------------------------------------------------------------------------
// Kernel 2: all-pairs loss. grid=(32,9), 256 thr, 2 blocks/SM, one wave.
// Block runs 4 jobs of 64x64: half-block (128 thr) per job, 2 job-rounds.
// Within a half: 16 row-positions x 8 col-groups; thread = 4 rows x 8 cols.
// Dot products in packed f32x2 (FFMA2); sigmoid via 2/(1+e^x) = 1-tanh(x/2)
// (exponent >= 0 always), tanh.approx = 1 MUFU/pair.
// SMEM rows padded to 5 float4 (80B) -> conflict-free / broadcast-friendly.
// ---------------------------------------------------------------------------
__global__ __launch_bounds__(256, 2) void tagloss_pairs_kernel(float* __restrict__ out) {
    __shared__ float4 sE[N_ * 5];   // 40 KB
    __shared__ float wsum[8];
    __shared__ float kwsum[8];

    const int b = blockIdx.x;
    const int jb = blockIdx.y;
    const int t = threadIdx.x;

    // Stage full batch tile (2560 float4).
    {
        const float4* gb = &g_ebd[b * N_ * 5];
#pragma unroll
        for (int k = 0; k < 10; ++k)
            sE[t + k * 256] = gb[t + k * 256];
    }
    __syncthreads();

    // K = sum(mask): 2 staged rows per thread (after barrier).
    float kp = sE[(t * 2) * 5 + 4].y + sE[(t * 2 + 1) * 5 + 4].y;
#pragma unroll
    for (int s = 16; s > 0; s >>= 1)
        kp += __shfl_xor_sync(0xFFFFFFFFu, kp, s);
    if ((t & 31) == 0) kwsum[t >> 5] = kp;

    const int half = t >> 7;          // which job of the pair this thread runs
    const int tt_ = t & 127;
    const int rpos = tt_ & 15;        // row position (rows strided by 16)
    const int cg = tt_ >> 4;          // column group 0..7 (8 cols each)

    float accT = 0.0f;

#pragma unroll
    for (int jk = 0; jk < 2; ++jk) {
        const int q = jb * 4 + half * 2 + jk;
        const int ti = JOB_TI[q];
        const int tj = JOB_TJ[q];
        const float w = (ti == tj) ? 1.0f : 2.0f;

        const int rbase = ti * 64 + rpos;
        const int cbase = tj * 64 + cg * 8;

        // Load + pack 4 A-rows (f32x2 pairs), meta.
        unsigned long long A2[4][8];
        float hrsq[4], rtag[4], rmask[4];
#pragma unroll
        for (int rr = 0; rr < 4; ++rr) {
            const int r = rbase + rr * 16;
#pragma unroll
            for (int j = 0; j < 4; ++j) {
                const float4 v = sE[r * 5 + j];
                A2[rr][2*j+0] = pk2(v.x, v.y);
                A2[rr][2*j+1] = pk2(v.z, v.w);
            }
            const float4 m = sE[r * 5 + 4];
            hrsq[rr] = 0.5f * m.x; rmask[rr] = m.y; rtag[rr] = m.z;
        }

        float acc[4] = {0.0f, 0.0f, 0.0f, 0.0f};
#pragma unroll
        for (int cc = 0; cc < 8; ++cc) {
            const int c = cbase + cc;
            unsigned long long C2[8];
#pragma unroll
            for (int j = 0; j < 4; ++j) {
                const float4 v = sE[c * 5 + j];
                C2[2*j+0] = pk2(v.x, v.y);
                C2[2*j+1] = pk2(v.z, v.w);
            }
            const float4 cm = sE[c * 5 + 4];
            const float hcsq = 0.5f * cm.x;
#pragma unroll
            for (int rr = 0; rr < 4; ++rr) {
                // two packed chains for ILP -> dot (16 MACs in 8 FFMA2)
                unsigned long long pa = mul2(A2[rr][0], C2[0]);
                unsigned long long pb = mul2(A2[rr][1], C2[1]);
                fma2(pa, A2[rr][2], C2[2]);
                fma2(pb, A2[rr][3], C2[3]);
                fma2(pa, A2[rr][4], C2[4]);
                fma2(pb, A2[rr][5], C2[5]);
                fma2(pa, A2[rr][6], C2[6]);
                fma2(pb, A2[rr][7], C2[7]);
                const float dot = hsum2(add2(pa, pb));
                // e/2 = 0.5*sq_r + 0.5*sq_c - dot   (>= 0)
                const float e2 = (hrsq[rr] + hcsq) - dot;
                // pred_sim - true_sim = (1 - tt) - tanh(e/2)
                const float c1 = (rtag[rr] == cm.z) ? 0.0f : 1.0f;
                const float d = c1 - tanh_approx(e2);
                acc[rr] = fmaf(cm.y, d * d, acc[rr]);
            }
        }
        accT += w * (rmask[0] * acc[0] + rmask[1] * acc[1] +
                     rmask[2] * acc[2] + rmask[3] * acc[3]);
    }

    // Block reduction + global accumulation.
#pragma unroll
    for (int s = 16; s > 0; s >>= 1)
        accT += __shfl_xor_sync(0xFFFFFFFFu, accT, s);
    if ((t & 31) == 0) wsum[t >> 5] = accT;
    __syncthreads();
    if (t == 0) {
        float total = 0.0f, K = 0.0f;
#pragma unroll
        for (int w = 0; w < 8; ++w) { total += wsum[w]; K += kwsum[w]; }
        const float scale = 10.0f / (fmaxf(K * K, 1.0f) * (float)B_);
        atomicAdd(out, total * scale);
    }
}

extern "C" void kernel_launch(void* const* d_in, const int* in_sizes, int n_in,
                              void* d_out, int out_size) {
    const float* pred = (const float*)d_in[0];
    const float* kpt  = (const float*)d_in[1];
    const int*   vis  = (const int*)d_in[2];
    const int*   tag  = (const int*)d_in[3];
    float* out = (float*)d_out;

    tagloss_gather_kernel<<<128, 128>>>(pred, kpt, vis, tag, out);
    dim3 grid(B_, 9);
    tagloss_pairs_kernel<<<grid, 256>>>(out);
}